// round 7
// baseline (speedup 1.0000x reference)
#include <cuda_runtime.h>
#include <math.h>

// R6 re-run: R5/R6 bench attempts died to container infra failure, not the
// kernel. Source is functionally identical to the R4 proposal.

#define DD 512
#define AA 256
#define BB 256
#define DSPLIT 4                             // grid.z of streaming kernel
#define ROWS_PER_BLOCK (DD / DSPLIT)         // 128
#define ROWS_PER_THREAD (ROWS_PER_BLOCK / 4) // 32

// DEPTHS = linspace(0,50,512) -> h = 50/511
// ANGLES = linspace(-30,30,256) -> step 60/255
// P = exp(-2*diff^2) masked by 0 < d/cos < 50, normalized over depth per column.
// exp(-2 z^2) = 2^(C2 z^2), C2 = -2/ln2; ex2.approx.ftz underflows to exact 0
// outside |z| ~ 4.6, so the write loop needs no window predicate.

__device__ float g_t[2 * BB * AA];    // d_theory per (which,b,angle)
__device__ float g_inv[2 * BB * AA];  // 1/colsum (0 if invalid column)

__device__ __forceinline__ float ex2_ftz(float x) {
    float r;
    asm("ex2.approx.ftz.f32 %0, %1;" : "=f"(r) : "f"(x));
    return r;
}

// ---- Kernel 1: per-column t and 1/sum, computed exactly once ----
__global__ void __launch_bounds__(AA)
precompute_kernel(const float* __restrict__ p, const float* __restrict__ pc)
{
    const int b     = blockIdx.x;
    const int which = blockIdx.y;
    const int a     = threadIdx.x;

    const float DEG2RAD  = 0.017453292519943295f;
    const float ANG_STEP = 60.0f / 255.0f;
    const float H        = 50.0f / 511.0f;
    const float INV_H    = 511.0f / 50.0f;
    const float C2       = -2.8853900817779268f;  // -2/ln2

    const float* src = which ? pc : p;
    const float d_val   = src[b * 3 + 1];
    const float theta_p = src[b * 3 + 2];

    const float angle = (theta_p + (-30.0f + (float)a * ANG_STEP)) * DEG2RAD;
    const float t = d_val / cosf(angle);   // accurate cosf: its error amplifies
                                           // through the Gaussian slope
    float inv = 0.0f;
    if (t > 0.0f && t < 50.0f) {
        // windowed sum: tail beyond |diff|=5 contributes < 1e-21
        int lo = max((int)ceilf((t - 5.0f) * INV_H), 0);
        int hi = min((int)floorf((t + 5.0f) * INV_H), DD - 1);
        float sum = 0.0f;
        for (int di = lo; di <= hi; ++di) {
            float z = (float)di * H - t;
            sum += ex2_ftz(C2 * z * z);
        }
        inv = (sum > 0.0f) ? (1.0f / sum) : 1.0f;
    }
    const int idx = (which * BB + b) * AA + a;
    g_t[idx]   = t;
    g_inv[idx] = inv;
}

// ---- Kernel 2: pure store streamer. No smem, no sync, no trig. ----
__global__ void __launch_bounds__(256, 8)
stream_kernel(float* __restrict__ out)
{
    const int b     = blockIdx.x;
    const int which = blockIdx.y;
    const int tid   = threadIdx.x;

    const float H  = 50.0f / 511.0f;
    const float C2 = -2.8853900817779268f;

    const int aq   = tid & 63;          // angle quad: angles 4*aq .. 4*aq+3
    const int dsub = tid >> 6;          // 0..3
    const int d0   = blockIdx.z * ROWS_PER_BLOCK + dsub * ROWS_PER_THREAD;
    const int a0   = aq * 4;

    const int cidx = (which * BB + b) * AA + a0;
    const float4 t4 = *(const float4*)(g_t + cidx);    // L2-resident, reused 16x
    const float4 i4 = *(const float4*)(g_inv + cidx);

    float z0 = (float)d0 * H - t4.x;
    float z1 = (float)d0 * H - t4.y;
    float z2 = (float)d0 * H - t4.z;
    float z3 = (float)d0 * H - t4.w;

    float4* outp = (float4*)(out
        + (((size_t)which * BB + b) * DD + d0) * (size_t)AA + a0);
    const int row_stride = AA / 4;

    #pragma unroll 8
    for (int r = 0; r < ROWS_PER_THREAD; ++r) {
        float4 v;
        v.x = ex2_ftz(C2 * z0 * z0) * i4.x;
        v.y = ex2_ftz(C2 * z1 * z1) * i4.y;
        v.z = ex2_ftz(C2 * z2 * z2) * i4.z;
        v.w = ex2_ftz(C2 * z3 * z3) * i4.w;
        __stcs(outp + (size_t)r * row_stride, v);   // streaming store, evict-first
        z0 += H; z1 += H; z2 += H; z3 += H;
    }
}

extern "C" void kernel_launch(void* const* d_in, const int* in_sizes, int n_in,
                              void* d_out, int out_size)
{
    const float* p  = (const float*)d_in[0];
    const float* pc = (const float*)d_in[1];
    float* out = (float*)d_out;

    precompute_kernel<<<dim3(BB, 2), AA>>>(p, pc);
    stream_kernel<<<dim3(BB, 2, DSPLIT), 256>>>(out);
}

// round 8
// speedup vs baseline: 1.1303x; 1.1303x over previous
#include <cuda_runtime.h>
#include <math.h>

#define DD 512
#define AA 256
#define BB 256
#define DSPLIT 4                             // grid.z
#define ROWS_PER_BLOCK (DD / DSPLIT)         // 128
#define ROWS_PER_THREAD (ROWS_PER_BLOCK / 4) // 32

// DEPTHS = linspace(0,50,512) -> h = 50/511; ANGLES = linspace(-30,30,256).
// P = exp(-2*diff^2) masked by 0 < d/cos < 50, normalized over depth.
//
// Key identity: sum_{n in Z} exp(-(nH-t)^2/(2 s^2)) = (s*sqrt(2pi)/H) *
// (1 + 2 exp(-2 pi^2 s^2 / H^2) cos(...)). With s=0.5, H=50/511 the correction
// is exp(-515) == 0, so whenever [t-5, t+5] is inside [0, 50] the discrete
// column sum equals the EXACT constant C = s*sqrt(2pi)/H. Only columns with
// t<5 or t>45 (clipped support) need the explicit windowed sum.

__device__ __forceinline__ float ex2_ftz(float x) {
    float r;
    asm("ex2.approx.ftz.f32 %0, %1;" : "=f"(r) : "f"(x));
    return r;
}

__global__ void __launch_bounds__(256, 8)
prior_kernel(const float* __restrict__ p,
             const float* __restrict__ pc,
             float* __restrict__ out)
{
    __shared__ float s_t[AA];
    __shared__ float s_inv[AA];

    const int b     = blockIdx.x;
    const int which = blockIdx.y;
    const int tid   = threadIdx.x;

    const float DEG2RAD  = 0.017453292519943295f;
    const float ANG_STEP = 60.0f / 255.0f;
    const float H        = 50.0f / 511.0f;
    const float INV_H    = 511.0f / 50.0f;
    const float C2       = -2.8853900817779268f;             // -2/ln2
    // 1/C = H / (sigma*sqrt(2*pi)), folded at compile time in double
    const float INV_C    = (float)((50.0 / 511.0) / (0.5 * 2.5066282746310002));

    // ---- Phase 1: per-column t and 1/colsum (thread tid <-> angle tid) ----
    {
        const float* src = which ? pc : p;
        const float d_val   = src[b * 3 + 1];
        const float theta_p = src[b * 3 + 2];

        const float angle = (theta_p + (-30.0f + (float)tid * ANG_STEP)) * DEG2RAD;
        const float t = d_val / cosf(angle);   // accurate cosf: error amplifies
                                               // through the Gaussian slope
        float inv = 0.0f;
        if (t > 0.0f && t < 50.0f) {
            if (t >= 5.0f && t <= 45.0f) {
                inv = INV_C;                   // unclipped: exact constant sum
            } else {
                // clipped column: explicit windowed sum (tail beyond |z|=5
                // contributes < 1e-21)
                int lo = max((int)ceilf((t - 5.0f) * INV_H), 0);
                int hi = min((int)floorf((t + 5.0f) * INV_H), DD - 1);
                float sum = 0.0f;
                for (int di = lo; di <= hi; ++di) {
                    float z = (float)di * H - t;
                    sum += ex2_ftz(C2 * z * z);
                }
                inv = (sum > 0.0f) ? (1.0f / sum) : 1.0f;
            }
        }
        s_t[tid]   = t;
        s_inv[tid] = inv;
    }
    __syncthreads();

    // ---- Phase 2: stream stores. Thread owns 4 angles x 32 depth rows. ----
    const int aq   = tid & 63;          // angle quad: angles 4*aq .. 4*aq+3
    const int dsub = tid >> 6;          // 0..3
    const int d0   = blockIdx.z * ROWS_PER_BLOCK + dsub * ROWS_PER_THREAD;
    const int a0   = aq * 4;

    const float t0 = s_t[a0 + 0], t1 = s_t[a0 + 1], t2 = s_t[a0 + 2], t3 = s_t[a0 + 3];
    const float i0 = s_inv[a0 + 0], i1 = s_inv[a0 + 1], i2 = s_inv[a0 + 2], i3 = s_inv[a0 + 3];

    float z0 = (float)d0 * H - t0;
    float z1 = (float)d0 * H - t1;
    float z2 = (float)d0 * H - t2;
    float z3 = (float)d0 * H - t3;

    float4* outp = (float4*)(out
        + (((size_t)which * BB + b) * DD + d0) * (size_t)AA + a0);
    const int row_stride = AA / 4;

    #pragma unroll 8
    for (int r = 0; r < ROWS_PER_THREAD; ++r) {
        float4 v;
        v.x = ex2_ftz(C2 * z0 * z0) * i0;   // ftz underflow -> exact 0 outside
        v.y = ex2_ftz(C2 * z1 * z1) * i1;   // the support, no predicate needed
        v.z = ex2_ftz(C2 * z2 * z2) * i2;
        v.w = ex2_ftz(C2 * z3 * z3) * i3;
        __stcs(outp + (size_t)r * row_stride, v);   // streaming, evict-first
        z0 += H; z1 += H; z2 += H; z3 += H;
    }
}

extern "C" void kernel_launch(void* const* d_in, const int* in_sizes, int n_in,
                              void* d_out, int out_size)
{
    const float* p  = (const float*)d_in[0];
    const float* pc = (const float*)d_in[1];
    float* out = (float*)d_out;

    prior_kernel<<<dim3(BB, 2, DSPLIT), 256>>>(p, pc, out);
}

// round 9
// speedup vs baseline: 1.2857x; 1.1375x over previous
#include <cuda_runtime.h>
#include <math.h>

#define DD 512
#define AA 256
#define BB 256
#define DSPLIT 8                             // grid.z  (R8: 4 -> 8, tail smoothing)
#define ROWS_PER_BLOCK (DD / DSPLIT)         // 64
#define ROWS_PER_THREAD (ROWS_PER_BLOCK / 4) // 16

// DEPTHS = linspace(0,50,512) -> h = 50/511; ANGLES = linspace(-30,30,256).
// P = exp(-2*diff^2) masked by 0 < d/cos < 50, normalized over depth.
//
// Poisson summation: sum_{n in Z} exp(-(nH-t)^2/(2 s^2)) = (s*sqrt(2pi)/H) *
// (1 + 2 exp(-2 pi^2 s^2 / H^2) cos(...)). With s=0.5, H=50/511 the correction
// is exp(-515) == 0, so whenever [t-5, t+5] lies inside [0, 50] the discrete
// column sum equals the EXACT constant C = s*sqrt(2pi)/H. Only columns with
// t<5 or t>45 (clipped support) need the explicit windowed sum.

__device__ __forceinline__ float ex2_ftz(float x) {
    float r;
    asm("ex2.approx.ftz.f32 %0, %1;" : "=f"(r) : "f"(x));
    return r;
}

__global__ void __launch_bounds__(256, 8)
prior_kernel(const float* __restrict__ p,
             const float* __restrict__ pc,
             float* __restrict__ out)
{
    __shared__ float s_t[AA];
    __shared__ float s_inv[AA];

    const int b     = blockIdx.x;
    const int which = blockIdx.y;
    const int tid   = threadIdx.x;

    const float DEG2RAD  = 0.017453292519943295f;
    const float ANG_STEP = 60.0f / 255.0f;
    const float H        = 50.0f / 511.0f;
    const float INV_H    = 511.0f / 50.0f;
    const float C2       = -2.8853900817779268f;             // -2/ln2
    // 1/C = H / (sigma*sqrt(2*pi)), folded at compile time in double
    const float INV_C    = (float)((50.0 / 511.0) / (0.5 * 2.5066282746310002));

    // ---- Phase 1: per-column t and 1/colsum (thread tid <-> angle tid) ----
    {
        const float* src = which ? pc : p;
        const float d_val   = src[b * 3 + 1];
        const float theta_p = src[b * 3 + 2];

        const float angle = (theta_p + (-30.0f + (float)tid * ANG_STEP)) * DEG2RAD;
        const float t = d_val / cosf(angle);   // accurate cosf: error amplifies
                                               // through the Gaussian slope
        float inv = 0.0f;
        if (t > 0.0f && t < 50.0f) {
            if (t >= 5.0f && t <= 45.0f) {
                inv = INV_C;                   // unclipped: exact constant sum
            } else {
                // clipped column: explicit windowed sum (tail beyond |z|=5
                // contributes < 1e-21)
                int lo = max((int)ceilf((t - 5.0f) * INV_H), 0);
                int hi = min((int)floorf((t + 5.0f) * INV_H), DD - 1);
                float sum = 0.0f;
                for (int di = lo; di <= hi; ++di) {
                    float z = (float)di * H - t;
                    sum += ex2_ftz(C2 * z * z);
                }
                inv = (sum > 0.0f) ? (1.0f / sum) : 1.0f;
            }
        }
        s_t[tid]   = t;
        s_inv[tid] = inv;
    }
    __syncthreads();

    // ---- Phase 2: stream stores. Thread owns 4 angles x 16 depth rows. ----
    const int aq   = tid & 63;          // angle quad: angles 4*aq .. 4*aq+3
    const int dsub = tid >> 6;          // 0..3
    const int d0   = blockIdx.z * ROWS_PER_BLOCK + dsub * ROWS_PER_THREAD;
    const int a0   = aq * 4;

    const float t0 = s_t[a0 + 0], t1 = s_t[a0 + 1], t2 = s_t[a0 + 2], t3 = s_t[a0 + 3];
    const float i0 = s_inv[a0 + 0], i1 = s_inv[a0 + 1], i2 = s_inv[a0 + 2], i3 = s_inv[a0 + 3];

    float z0 = (float)d0 * H - t0;
    float z1 = (float)d0 * H - t1;
    float z2 = (float)d0 * H - t2;
    float z3 = (float)d0 * H - t3;

    float4* outp = (float4*)(out
        + (((size_t)which * BB + b) * DD + d0) * (size_t)AA + a0);
    const int row_stride = AA / 4;

    #pragma unroll
    for (int r = 0; r < ROWS_PER_THREAD; ++r) {
        float4 v;
        v.x = ex2_ftz(C2 * z0 * z0) * i0;   // ftz underflow -> exact 0 outside
        v.y = ex2_ftz(C2 * z1 * z1) * i1;   // the support, no predicate needed
        v.z = ex2_ftz(C2 * z2 * z2) * i2;
        v.w = ex2_ftz(C2 * z3 * z3) * i3;
        __stcs(outp + (size_t)r * row_stride, v);   // streaming, evict-first
        z0 += H; z1 += H; z2 += H; z3 += H;
    }
}

extern "C" void kernel_launch(void* const* d_in, const int* in_sizes, int n_in,
                              void* d_out, int out_size)
{
    const float* p  = (const float*)d_in[0];
    const float* pc = (const float*)d_in[1];
    float* out = (float*)d_out;

    prior_kernel<<<dim3(BB, 2, DSPLIT), 256>>>(p, pc, out);
}